// round 1
// baseline (speedup 1.0000x reference)
#include <cuda_runtime.h>
#include <cuda_bf16.h>
#include <cstdint>

#define NN 50000
#define EE 800000
#define DIM 256

// ---- scratch (static device globals: no allocation allowed) ----
__device__ float d_bufA[(size_t)NN * DIM];   // 51.2 MB
__device__ float d_bufB[(size_t)NN * DIM];   // 51.2 MB
__device__ float d_deg[NN];
__device__ float d_dinv[NN];
__device__ float d_mean[DIM];

// ---- degree: deg[i] = #incoming edges (self loop added analytically later) ----
__global__ void k_deg(const int* __restrict__ dst, int E, float* __restrict__ deg) {
    int e = blockIdx.x * blockDim.x + threadIdx.x;
    if (e < E) atomicAdd(&deg[dst[e]], 1.0f);
}

__global__ void k_dinv(const float* __restrict__ deg, float* __restrict__ dinv, int n) {
    int i = blockIdx.x * blockDim.x + threadIdx.x;
    if (i < n) dinv[i] = rsqrtf(deg[i] + 1.0f);   // +1 = self loop
}

// ---- fp32 SGEMM: C[M,256] = A[M,256] @ B[256,256], 64x64 tiles, 4x4 per thread ----
__global__ void k_gemm(const float* __restrict__ A, const float* __restrict__ B,
                       float* __restrict__ C, int M) {
    const int K = 256, N = 256;
    __shared__ float As[16][68];   // [k][m], row = 272B (16B-aligned)
    __shared__ float Bs[16][68];   // [k][n]
    int t = threadIdx.x;           // 256 threads
    int tx = t & 15, ty = t >> 4;
    int m0 = blockIdx.y * 64, n0 = blockIdx.x * 64;
    int arow = t >> 2, acol = (t & 3) * 4;   // A tile 64x16, float4 per thread
    int brow = t >> 4, bcol = (t & 15) * 4;  // B tile 16x64, float4 per thread
    float acc[4][4] = {};
    for (int k0 = 0; k0 < K; k0 += 16) {
        float4 av = make_float4(0.f, 0.f, 0.f, 0.f);
        if (m0 + arow < M)
            av = *(const float4*)(A + (size_t)(m0 + arow) * K + k0 + acol);
        As[acol + 0][arow] = av.x;
        As[acol + 1][arow] = av.y;
        As[acol + 2][arow] = av.z;
        As[acol + 3][arow] = av.w;
        *(float4*)&Bs[brow][bcol] =
            *(const float4*)(B + (size_t)(k0 + brow) * N + n0 + bcol);
        __syncthreads();
        #pragma unroll
        for (int kk = 0; kk < 16; kk++) {
            float4 a4 = *(const float4*)&As[kk][ty * 4];
            float4 b4 = *(const float4*)&Bs[kk][tx * 4];
            float a[4] = {a4.x, a4.y, a4.z, a4.w};
            float b[4] = {b4.x, b4.y, b4.z, b4.w};
            #pragma unroll
            for (int i = 0; i < 4; i++)
                #pragma unroll
                for (int j = 0; j < 4; j++)
                    acc[i][j] = fmaf(a[i], b[j], acc[i][j]);
        }
        __syncthreads();
    }
    #pragma unroll
    for (int i = 0; i < 4; i++) {
        int m = m0 + ty * 4 + i;
        if (m < M) {
            float4 r = make_float4(acc[i][0], acc[i][1], acc[i][2], acc[i][3]);
            *(float4*)(C + (size_t)m * N + n0 + tx * 4) = r;
        }
    }
}

// ---- edge scatter: out[dst] += dinv[src]*dinv[dst] * H[src]  (vector red) ----
__global__ void k_scatter(const float4* __restrict__ H, float* __restrict__ out,
                          const int* __restrict__ src, const int* __restrict__ dst,
                          const float* __restrict__ dinv, int E) {
    long long idx = (long long)blockIdx.x * blockDim.x + threadIdx.x;
    long long total = (long long)E * 64;
    if (idx >= total) return;
    int e = (int)(idx >> 6);
    int c = (int)(idx & 63);
    int s = src[e], d = dst[e];
    float w = dinv[s] * dinv[d];
    float4 v = H[(long long)s * 64 + c];
    float* p = out + (long long)d * DIM + c * 4;
    asm volatile("red.global.add.v4.f32 [%0], {%1, %2, %3, %4};"
                 :: "l"(p), "f"(v.x * w), "f"(v.y * w), "f"(v.z * w), "f"(v.w * w)
                 : "memory");
}

// ---- epilogue: A = relu(A + dinv[i]^2 * H[i] + bias)  (self-loop fused) ----
__global__ void k_epilogue(const float4* __restrict__ H, float4* __restrict__ A,
                           const float* __restrict__ dinv,
                           const float4* __restrict__ bias, int n) {
    long long idx = (long long)blockIdx.x * blockDim.x + threadIdx.x;
    long long total = (long long)n * 64;
    if (idx >= total) return;
    int i = (int)(idx >> 6);
    int c = (int)(idx & 63);
    float w = dinv[i];
    w = w * w;
    float4 h = H[idx], a = A[idx], b = bias[c];
    float4 r;
    r.x = fmaxf(fmaf(w, h.x, a.x) + b.x, 0.f);
    r.y = fmaxf(fmaf(w, h.y, a.y) + b.y, 0.f);
    r.z = fmaxf(fmaf(w, h.z, a.z) + b.z, 0.f);
    r.w = fmaxf(fmaf(w, h.w, a.w) + b.w, 0.f);
    A[idx] = r;
}

// ---- column sums for mean pooling ----
__global__ void k_colsum(const float* __restrict__ A, float* __restrict__ mean, int n) {
    int j = threadIdx.x;   // 256
    float s = 0.f;
    for (int i = blockIdx.x; i < n; i += gridDim.x)
        s += A[(long long)i * DIM + j];
    atomicAdd(&mean[j], s);
}

// ---- MLP head: relu(mean/N) -> fc1 -> relu -> fc2 -> relu -> fc3 ----
__global__ void k_head(const float* __restrict__ mean,
                       const float* __restrict__ fcW1, const float* __restrict__ fcb1,
                       const float* __restrict__ fcW2, const float* __restrict__ fcb2,
                       const float* __restrict__ fcW3, const float* __restrict__ fcb3,
                       float* __restrict__ out, int n) {
    __shared__ float g[256], h[256];
    int j = threadIdx.x;
    g[j] = fmaxf(mean[j] * (1.0f / (float)n), 0.f);
    __syncthreads();
    float s = fcb1[j];
    #pragma unroll 8
    for (int i = 0; i < 256; i++) s = fmaf(g[i], fcW1[i * 256 + j], s);
    h[j] = fmaxf(s, 0.f);
    __syncthreads();
    s = fcb2[j];
    #pragma unroll 8
    for (int i = 0; i < 256; i++) s = fmaf(h[i], fcW2[i * 256 + j], s);
    float g2 = fmaxf(s, 0.f);
    __syncthreads();
    g[j] = g2;
    __syncthreads();
    if (j < 64) {
        s = fcb3[j];
        #pragma unroll 8
        for (int i = 0; i < 256; i++) s = fmaf(g[i], fcW3[i * 64 + j], s);
        out[j] = s;
    }
}

extern "C" void kernel_launch(void* const* d_in, const int* in_sizes, int n_in,
                              void* d_out, int out_size) {
    const float* x    = (const float*)d_in[0];
    const int*   ei   = (const int*)  d_in[1];   // [2, E] int32
    const float* W1   = (const float*)d_in[2];
    const float* b1   = (const float*)d_in[3];
    const float* W2   = (const float*)d_in[4];
    const float* b2   = (const float*)d_in[5];
    const float* fcW1 = (const float*)d_in[6];
    const float* fcb1 = (const float*)d_in[7];
    const float* fcW2 = (const float*)d_in[8];
    const float* fcb2 = (const float*)d_in[9];
    const float* fcW3 = (const float*)d_in[10];
    const float* fcb3 = (const float*)d_in[11];
    float* out = (float*)d_out;

    int E = in_sizes[1] / 2;
    int N = in_sizes[0] / DIM;
    const int* src = ei;
    const int* dst = ei + E;

    float *bufA, *bufB, *deg, *dinv, *mean;
    cudaGetSymbolAddress((void**)&bufA, d_bufA);
    cudaGetSymbolAddress((void**)&bufB, d_bufB);
    cudaGetSymbolAddress((void**)&deg,  d_deg);
    cudaGetSymbolAddress((void**)&dinv, d_dinv);
    cudaGetSymbolAddress((void**)&mean, d_mean);

    // normalization
    cudaMemsetAsync(deg, 0, (size_t)N * sizeof(float));
    k_deg<<<(E + 255) / 256, 256>>>(dst, E, deg);
    k_dinv<<<(N + 255) / 256, 256>>>(deg, dinv, N);

    dim3 gg(DIM / 64, (N + 63) / 64);
    long long etot = (long long)E * 64;
    long long ntot = (long long)N * 64;
    unsigned eblocks = (unsigned)((etot + 255) / 256);
    unsigned nblocks = (unsigned)((ntot + 255) / 256);

    // layer 1: H1 = X@W1 ; A1 = relu(scatter(H1) + selfloop + b1)
    k_gemm<<<gg, 256>>>(x, W1, bufA, N);
    cudaMemsetAsync(bufB, 0, (size_t)N * DIM * sizeof(float));
    k_scatter<<<eblocks, 256>>>((const float4*)bufA, bufB, src, dst, dinv, E);
    k_epilogue<<<nblocks, 256>>>((const float4*)bufA, (float4*)bufB, dinv,
                                 (const float4*)b1, N);

    // layer 2: H2 = A1@W2 ; A2 = relu(scatter(H2) + selfloop + b2)
    k_gemm<<<gg, 256>>>(bufB, W2, bufA, N);
    cudaMemsetAsync(bufB, 0, (size_t)N * DIM * sizeof(float));
    k_scatter<<<eblocks, 256>>>((const float4*)bufA, bufB, src, dst, dinv, E);
    k_epilogue<<<nblocks, 256>>>((const float4*)bufA, (float4*)bufB, dinv,
                                 (const float4*)b2, N);

    // mean pool + head
    cudaMemsetAsync(mean, 0, DIM * sizeof(float));
    k_colsum<<<256, 256>>>(bufB, mean, N);
    k_head<<<1, 256>>>(mean, fcW1, fcb1, fcW2, fcb2, fcW3, fcb3, out, N);
}

// round 2
// speedup vs baseline: 2.0283x; 2.0283x over previous
#include <cuda_runtime.h>
#include <cuda_bf16.h>
#include <cstdint>

#define NN 50000
#define EE 800000
#define DIM 256

// ---- scratch (static device globals: no allocation allowed) ----
__device__ float d_bufA[(size_t)NN * DIM];   // 51.2 MB
__device__ float d_bufB[(size_t)NN * DIM];   // 51.2 MB
__device__ int   d_degi[NN];
__device__ float d_dinv[NN];
__device__ float d_mean[DIM];
__device__ int   d_rowstart[NN + 1];
__device__ int   d_cursor[NN];
__device__ int   d_csr[EE];

// ---------------- degree (int) ----------------
__global__ void k_deg(const int* __restrict__ dst, int E, int* __restrict__ deg) {
    int e = blockIdx.x * blockDim.x + threadIdx.x;
    if (e < E) atomicAdd(&deg[dst[e]], 1);
}

__global__ void k_dinv(const int* __restrict__ deg, float* __restrict__ dinv, int n) {
    int i = blockIdx.x * blockDim.x + threadIdx.x;
    if (i < n) dinv[i] = rsqrtf((float)deg[i] + 1.0f);   // +1 = self loop
}

// ---------------- exclusive scan (single block, 1024 threads) ----------------
__global__ void k_scan(const int* __restrict__ deg, int* __restrict__ rowstart, int n) {
    __shared__ int partial[1024];
    int t = threadIdx.x;
    int chunk = (n + 1023) >> 10;
    int beg = t * chunk;
    int end = min(beg + chunk, n);
    int s = 0;
    for (int i = beg; i < end; i++) s += deg[i];
    partial[t] = s;
    __syncthreads();
    for (int off = 1; off < 1024; off <<= 1) {
        int add = (t >= off) ? partial[t - off] : 0;
        __syncthreads();
        partial[t] += add;
        __syncthreads();
    }
    int excl = (t == 0) ? 0 : partial[t - 1];
    for (int i = beg; i < end; i++) { rowstart[i] = excl; excl += deg[i]; }
    if (end == n) rowstart[n] = excl;
}

// ---------------- CSR fill ----------------
__global__ void k_fill(const int* __restrict__ src, const int* __restrict__ dst,
                       int* __restrict__ cursor, int* __restrict__ csr, int E) {
    int e = blockIdx.x * blockDim.x + threadIdx.x;
    if (e < E) {
        int d = dst[e];
        int pos = atomicAdd(&cursor[d], 1);
        csr[pos] = src[e];
    }
}

// ---------------- TF32 tensor-core GEMM: C[M,256] = A[M,256] @ B[256,256] ----------------
__device__ __forceinline__ unsigned f2tf32(float f) {
    unsigned u;
    asm("cvt.rna.tf32.f32 %0, %1;" : "=r"(u) : "f"(f));
    return u;
}

__global__ void __launch_bounds__(256, 2)
k_gemm_tf32(const float* __restrict__ A, const float* __restrict__ B,
            float* __restrict__ C, int M) {
    const int BK_P = 36, BN_P = 132;
    __shared__ float As[128][BK_P];   // [m][k]
    __shared__ float Bs[32][BN_P];    // [k][n]
    int t = threadIdx.x;
    int lane = t & 31, wid = t >> 5;
    int wm = wid & 1, wn = wid >> 1;          // warp tile: 64x32
    int gi = lane >> 2, ti = lane & 3;
    int m0 = blockIdx.y * 128, n0 = blockIdx.x * 128;

    float acc[4][4][4];
    #pragma unroll
    for (int i = 0; i < 4; i++)
        #pragma unroll
        for (int j = 0; j < 4; j++)
            acc[i][j][0] = acc[i][j][1] = acc[i][j][2] = acc[i][j][3] = 0.f;

    for (int k0 = 0; k0 < 256; k0 += 32) {
        // load A tile 128x32 (tf32-rounded)
        #pragma unroll
        for (int i = 0; i < 4; i++) {
            int idx = t + i * 256;
            int ar = idx >> 3, ac = (idx & 7) * 4;
            float4 v = make_float4(0.f, 0.f, 0.f, 0.f);
            int row = m0 + ar;
            if (row < M) v = *(const float4*)(A + (size_t)row * 256 + k0 + ac);
            float4 w;
            w.x = __uint_as_float(f2tf32(v.x));
            w.y = __uint_as_float(f2tf32(v.y));
            w.z = __uint_as_float(f2tf32(v.z));
            w.w = __uint_as_float(f2tf32(v.w));
            *(float4*)&As[ar][ac] = w;
        }
        // load B tile 32x128
        #pragma unroll
        for (int i = 0; i < 4; i++) {
            int idx = t + i * 256;
            int br = idx >> 5, bc = (idx & 31) * 4;
            float4 v = *(const float4*)(B + (size_t)(k0 + br) * 256 + n0 + bc);
            float4 w;
            w.x = __uint_as_float(f2tf32(v.x));
            w.y = __uint_as_float(f2tf32(v.y));
            w.z = __uint_as_float(f2tf32(v.z));
            w.w = __uint_as_float(f2tf32(v.w));
            *(float4*)&Bs[br][bc] = w;
        }
        __syncthreads();
        #pragma unroll
        for (int kk = 0; kk < 4; kk++) {
            int kb = kk * 8;
            unsigned a[4][4], b[4][2];
            #pragma unroll
            for (int mt = 0; mt < 4; mt++) {
                int r = wm * 64 + mt * 16 + gi;
                a[mt][0] = __float_as_uint(As[r][kb + ti]);
                a[mt][1] = __float_as_uint(As[r + 8][kb + ti]);
                a[mt][2] = __float_as_uint(As[r][kb + ti + 4]);
                a[mt][3] = __float_as_uint(As[r + 8][kb + ti + 4]);
            }
            #pragma unroll
            for (int nt = 0; nt < 4; nt++) {
                int cn = wn * 32 + nt * 8 + gi;
                b[nt][0] = __float_as_uint(Bs[kb + ti][cn]);
                b[nt][1] = __float_as_uint(Bs[kb + ti + 4][cn]);
            }
            #pragma unroll
            for (int mt = 0; mt < 4; mt++)
                #pragma unroll
                for (int nt = 0; nt < 4; nt++)
                    asm volatile(
                        "mma.sync.aligned.m16n8k8.row.col.f32.tf32.tf32.f32 "
                        "{%0,%1,%2,%3}, {%4,%5,%6,%7}, {%8,%9}, {%0,%1,%2,%3};"
                        : "+f"(acc[mt][nt][0]), "+f"(acc[mt][nt][1]),
                          "+f"(acc[mt][nt][2]), "+f"(acc[mt][nt][3])
                        : "r"(a[mt][0]), "r"(a[mt][1]), "r"(a[mt][2]), "r"(a[mt][3]),
                          "r"(b[nt][0]), "r"(b[nt][1]));
        }
        __syncthreads();
    }
    #pragma unroll
    for (int mt = 0; mt < 4; mt++)
        #pragma unroll
        for (int nt = 0; nt < 4; nt++) {
            int row = m0 + wm * 64 + mt * 16 + gi;
            int col = n0 + wn * 32 + nt * 8 + ti * 2;
            if (row < M)
                *(float2*)(C + (size_t)row * 256 + col) =
                    make_float2(acc[mt][nt][0], acc[mt][nt][1]);
            if (row + 8 < M)
                *(float2*)(C + (size_t)(row + 8) * 256 + col) =
                    make_float2(acc[mt][nt][2], acc[mt][nt][3]);
        }
}

// ---------------- CSR gather + self-loop + bias + relu (fused) ----------------
__global__ void k_gather(const float4* __restrict__ H, float4* __restrict__ out,
                         const int* __restrict__ rowstart, const int* __restrict__ csr,
                         const float* __restrict__ dinv,
                         const float4* __restrict__ bias, int n) {
    int node = blockIdx.x * 4 + (threadIdx.x >> 6);
    if (node >= n) return;
    int c = threadIdx.x & 63;
    int r0 = rowstart[node], r1 = rowstart[node + 1];
    float di = dinv[node];
    float4 h = H[(size_t)node * 64 + c];
    float4 acc = make_float4(di * h.x, di * h.y, di * h.z, di * h.w);  // self loop
    int e = r0;
    for (; e + 1 < r1; e += 2) {
        int s0 = csr[e], s1 = csr[e + 1];
        float w0 = dinv[s0], w1 = dinv[s1];
        float4 v0 = H[(size_t)s0 * 64 + c];
        float4 v1 = H[(size_t)s1 * 64 + c];
        acc.x = fmaf(w0, v0.x, acc.x); acc.y = fmaf(w0, v0.y, acc.y);
        acc.z = fmaf(w0, v0.z, acc.z); acc.w = fmaf(w0, v0.w, acc.w);
        acc.x = fmaf(w1, v1.x, acc.x); acc.y = fmaf(w1, v1.y, acc.y);
        acc.z = fmaf(w1, v1.z, acc.z); acc.w = fmaf(w1, v1.w, acc.w);
    }
    if (e < r1) {
        int s0 = csr[e];
        float w0 = dinv[s0];
        float4 v0 = H[(size_t)s0 * 64 + c];
        acc.x = fmaf(w0, v0.x, acc.x); acc.y = fmaf(w0, v0.y, acc.y);
        acc.z = fmaf(w0, v0.z, acc.z); acc.w = fmaf(w0, v0.w, acc.w);
    }
    float4 b = bias[c];
    float4 r;
    r.x = fmaxf(fmaf(di, acc.x, b.x), 0.f);
    r.y = fmaxf(fmaf(di, acc.y, b.y), 0.f);
    r.z = fmaxf(fmaf(di, acc.z, b.z), 0.f);
    r.w = fmaxf(fmaf(di, acc.w, b.w), 0.f);
    out[(size_t)node * 64 + c] = r;
}

// ---------------- column sums for mean pooling ----------------
__global__ void k_colsum(const float* __restrict__ A, float* __restrict__ mean, int n) {
    int j = threadIdx.x;   // 256
    float s = 0.f;
    for (int i = blockIdx.x; i < n; i += gridDim.x)
        s += A[(size_t)i * DIM + j];
    atomicAdd(&mean[j], s);
}

// ---------------- MLP head ----------------
__global__ void k_head(const float* __restrict__ mean,
                       const float* __restrict__ fcW1, const float* __restrict__ fcb1,
                       const float* __restrict__ fcW2, const float* __restrict__ fcb2,
                       const float* __restrict__ fcW3, const float* __restrict__ fcb3,
                       float* __restrict__ out, int n) {
    __shared__ float g[256], h[256];
    int j = threadIdx.x;
    g[j] = fmaxf(mean[j] * (1.0f / (float)n), 0.f);
    __syncthreads();
    float s = fcb1[j];
    #pragma unroll 8
    for (int i = 0; i < 256; i++) s = fmaf(g[i], fcW1[i * 256 + j], s);
    h[j] = fmaxf(s, 0.f);
    __syncthreads();
    s = fcb2[j];
    #pragma unroll 8
    for (int i = 0; i < 256; i++) s = fmaf(h[i], fcW2[i * 256 + j], s);
    float g2 = fmaxf(s, 0.f);
    __syncthreads();
    g[j] = g2;
    __syncthreads();
    if (j < 64) {
        s = fcb3[j];
        #pragma unroll 8
        for (int i = 0; i < 256; i++) s = fmaf(g[i], fcW3[i * 64 + j], s);
        out[j] = s;
    }
}

extern "C" void kernel_launch(void* const* d_in, const int* in_sizes, int n_in,
                              void* d_out, int out_size) {
    const float* x    = (const float*)d_in[0];
    const int*   ei   = (const int*)  d_in[1];   // [2, E] int32
    const float* W1   = (const float*)d_in[2];
    const float* b1   = (const float*)d_in[3];
    const float* W2   = (const float*)d_in[4];
    const float* b2   = (const float*)d_in[5];
    const float* fcW1 = (const float*)d_in[6];
    const float* fcb1 = (const float*)d_in[7];
    const float* fcW2 = (const float*)d_in[8];
    const float* fcb2 = (const float*)d_in[9];
    const float* fcW3 = (const float*)d_in[10];
    const float* fcb3 = (const float*)d_in[11];
    float* out = (float*)d_out;

    int E = in_sizes[1] / 2;
    int N = in_sizes[0] / DIM;
    const int* src = ei;
    const int* dst = ei + E;

    float *bufA, *bufB, *dinv, *mean;
    int *degi, *rowstart, *cursor, *csr;
    cudaGetSymbolAddress((void**)&bufA, d_bufA);
    cudaGetSymbolAddress((void**)&bufB, d_bufB);
    cudaGetSymbolAddress((void**)&degi, d_degi);
    cudaGetSymbolAddress((void**)&dinv, d_dinv);
    cudaGetSymbolAddress((void**)&mean, d_mean);
    cudaGetSymbolAddress((void**)&rowstart, d_rowstart);
    cudaGetSymbolAddress((void**)&cursor, d_cursor);
    cudaGetSymbolAddress((void**)&csr, d_csr);

    // ---- normalization + CSR build ----
    cudaMemsetAsync(degi, 0, (size_t)N * sizeof(int));
    k_deg<<<(E + 255) / 256, 256>>>(dst, E, degi);
    k_scan<<<1, 1024>>>(degi, rowstart, N);
    cudaMemcpyAsync(cursor, rowstart, (size_t)N * sizeof(int),
                    cudaMemcpyDeviceToDevice);
    k_fill<<<(E + 255) / 256, 256>>>(src, dst, cursor, csr, E);
    k_dinv<<<(N + 255) / 256, 256>>>(degi, dinv, N);

    dim3 gg(2, (N + 127) / 128);
    unsigned gblocks = (unsigned)((N + 3) / 4);

    // ---- layer 1 ----
    k_gemm_tf32<<<gg, 256>>>(x, W1, bufA, N);
    k_gather<<<gblocks, 256>>>((const float4*)bufA, (float4*)bufB,
                               rowstart, csr, dinv, (const float4*)b1, N);
    // ---- layer 2 ----
    k_gemm_tf32<<<gg, 256>>>(bufB, W2, bufA, N);
    k_gather<<<gblocks, 256>>>((const float4*)bufA, (float4*)bufB,
                               rowstart, csr, dinv, (const float4*)b2, N);

    // ---- mean pool + head ----
    cudaMemsetAsync(mean, 0, DIM * sizeof(float));
    k_colsum<<<256, 256>>>(bufB, mean, N);
    k_head<<<1, 256>>>(mean, fcW1, fcb1, fcW2, fcb2, fcW3, fcb3, out, N);
}

// round 4
// speedup vs baseline: 2.2787x; 1.1234x over previous
#include <cuda_runtime.h>
#include <cuda_bf16.h>
#include <cstdint>

#define NN 50000
#define EE 800000
#define DIM 256

// ---- scratch (static device globals) ----
__device__ __nv_bfloat16 d_h[(size_t)NN * DIM];   // 25.6 MB  (GEMM output H)
__device__ __nv_bfloat16 d_a[(size_t)NN * DIM];   // 25.6 MB  (post-aggregation activations)
__device__ int   d_degi[NN];
__device__ float d_dinv[NN];
__device__ float d_mean[DIM];
__device__ int   d_rowstart[NN + 1];
__device__ int   d_cursor[NN];
__device__ int   d_csr[EE];

// ---------------- degree ----------------
__global__ void k_deg(const int* __restrict__ dst, int E, int* __restrict__ deg) {
    int e = blockIdx.x * blockDim.x + threadIdx.x;
    if (e < E) atomicAdd(&deg[dst[e]], 1);
}

// ---------------- fused scan: rowstart + cursor + dinv ----------------
__global__ void k_scan(const int* __restrict__ deg, int* __restrict__ rowstart,
                       int* __restrict__ cursor, float* __restrict__ dinv, int n) {
    __shared__ int partial[1024];
    int t = threadIdx.x;
    int chunk = (n + 1023) >> 10;
    int beg = t * chunk;
    int end = min(beg + chunk, n);
    int s = 0;
    for (int i = beg; i < end; i++) s += deg[i];
    partial[t] = s;
    __syncthreads();
    for (int off = 1; off < 1024; off <<= 1) {
        int add = (t >= off) ? partial[t - off] : 0;
        __syncthreads();
        partial[t] += add;
        __syncthreads();
    }
    int excl = (t == 0) ? 0 : partial[t - 1];
    for (int i = beg; i < end; i++) {
        rowstart[i] = excl;
        cursor[i] = excl;
        dinv[i] = rsqrtf((float)deg[i] + 1.0f);   // +1 = self loop
        excl += deg[i];
    }
    if (end == n) rowstart[n] = excl;
}

// ---------------- CSR fill ----------------
__global__ void k_fill(const int* __restrict__ src, const int* __restrict__ dst,
                       int* __restrict__ cursor, int* __restrict__ csr, int E) {
    int e = blockIdx.x * blockDim.x + threadIdx.x;
    if (e < E) {
        int pos = atomicAdd(&cursor[dst[e]], 1);
        csr[pos] = src[e];
    }
}

// ---------------- TF32 tensor-core GEMM, bf16 output ----------------
__device__ __forceinline__ unsigned f2tf32(float f) {
    unsigned u;
    asm("cvt.rna.tf32.f32 %0, %1;" : "=r"(u) : "f"(f));
    return u;
}

template <bool BF16IN>
__global__ void __launch_bounds__(256, 2)
k_gemm(const void* __restrict__ Aptr, const float* __restrict__ B,
       __nv_bfloat162* __restrict__ C, int M) {
    const int BK_P = 36, BN_P = 132;
    __shared__ float As[128][BK_P];   // [m][k]
    __shared__ float Bs[32][BN_P];    // [k][n]
    int t = threadIdx.x;
    int lane = t & 31, wid = t >> 5;
    int wm = wid & 1, wn = wid >> 1;          // warp tile: 64x32
    int gi = lane >> 2, ti = lane & 3;
    int m0 = blockIdx.y * 128, n0 = blockIdx.x * 128;

    float acc[4][4][4];
    #pragma unroll
    for (int i = 0; i < 4; i++)
        #pragma unroll
        for (int j = 0; j < 4; j++)
            acc[i][j][0] = acc[i][j][1] = acc[i][j][2] = acc[i][j][3] = 0.f;

    for (int k0 = 0; k0 < 256; k0 += 32) {
        if (BF16IN) {
            const __nv_bfloat16* A = (const __nv_bfloat16*)Aptr;
            #pragma unroll
            for (int i = 0; i < 2; i++) {
                int idx = t + i * 256;          // 512 slots of 8 elems
                int ar = idx >> 2, ac = (idx & 3) * 8;
                int row = m0 + ar;
                float f[8];
                if (row < M) {
                    uint4 v = *(const uint4*)(A + (size_t)row * 256 + k0 + ac);
                    const __nv_bfloat162* p = (const __nv_bfloat162*)&v;
                    #pragma unroll
                    for (int j = 0; j < 4; j++) {
                        float2 t2 = __bfloat1622float2(p[j]);
                        f[2 * j] = t2.x; f[2 * j + 1] = t2.y;
                    }
                } else {
                    #pragma unroll
                    for (int j = 0; j < 8; j++) f[j] = 0.f;
                }
                // bf16 values are exact in tf32 — no cvt needed
                *(float4*)&As[ar][ac]     = make_float4(f[0], f[1], f[2], f[3]);
                *(float4*)&As[ar][ac + 4] = make_float4(f[4], f[5], f[6], f[7]);
            }
        } else {
            const float* A = (const float*)Aptr;
            #pragma unroll
            for (int i = 0; i < 4; i++) {
                int idx = t + i * 256;
                int ar = idx >> 3, ac = (idx & 7) * 4;
                float4 v = make_float4(0.f, 0.f, 0.f, 0.f);
                int row = m0 + ar;
                if (row < M) v = *(const float4*)(A + (size_t)row * 256 + k0 + ac);
                float4 w;
                w.x = __uint_as_float(f2tf32(v.x));
                w.y = __uint_as_float(f2tf32(v.y));
                w.z = __uint_as_float(f2tf32(v.z));
                w.w = __uint_as_float(f2tf32(v.w));
                *(float4*)&As[ar][ac] = w;
            }
        }
        #pragma unroll
        for (int i = 0; i < 4; i++) {
            int idx = t + i * 256;
            int br = idx >> 5, bc = (idx & 31) * 4;
            float4 v = *(const float4*)(B + (size_t)(k0 + br) * 256 + n0 + bc);
            float4 w;
            w.x = __uint_as_float(f2tf32(v.x));
            w.y = __uint_as_float(f2tf32(v.y));
            w.z = __uint_as_float(f2tf32(v.z));
            w.w = __uint_as_float(f2tf32(v.w));
            *(float4*)&Bs[br][bc] = w;
        }
        __syncthreads();
        #pragma unroll
        for (int kk = 0; kk < 4; kk++) {
            int kb = kk * 8;
            unsigned a[4][4], b[4][2];
            #pragma unroll
            for (int mt = 0; mt < 4; mt++) {
                int r = wm * 64 + mt * 16 + gi;
                a[mt][0] = __float_as_uint(As[r][kb + ti]);
                a[mt][1] = __float_as_uint(As[r + 8][kb + ti]);
                a[mt][2] = __float_as_uint(As[r][kb + ti + 4]);
                a[mt][3] = __float_as_uint(As[r + 8][kb + ti + 4]);
            }
            #pragma unroll
            for (int nt = 0; nt < 4; nt++) {
                int cn = wn * 32 + nt * 8 + gi;
                b[nt][0] = __float_as_uint(Bs[kb + ti][cn]);
                b[nt][1] = __float_as_uint(Bs[kb + ti + 4][cn]);
            }
            #pragma unroll
            for (int mt = 0; mt < 4; mt++)
                #pragma unroll
                for (int nt = 0; nt < 4; nt++)
                    asm volatile(
                        "mma.sync.aligned.m16n8k8.row.col.f32.tf32.tf32.f32 "
                        "{%0,%1,%2,%3}, {%4,%5,%6,%7}, {%8,%9}, {%0,%1,%2,%3};"
                        : "+f"(acc[mt][nt][0]), "+f"(acc[mt][nt][1]),
                          "+f"(acc[mt][nt][2]), "+f"(acc[mt][nt][3])
                        : "r"(a[mt][0]), "r"(a[mt][1]), "r"(a[mt][2]), "r"(a[mt][3]),
                          "r"(b[nt][0]), "r"(b[nt][1]));
        }
        __syncthreads();
    }
    #pragma unroll
    for (int mt = 0; mt < 4; mt++)
        #pragma unroll
        for (int nt = 0; nt < 4; nt++) {
            int row = m0 + wm * 64 + mt * 16 + gi;
            // FIX: include block-column offset n0/2 in the bf16x2 pair index
            int pc = n0 / 2 + wn * 16 + nt * 4 + ti;
            if (row < M)
                C[(size_t)row * 128 + pc] =
                    __floats2bfloat162_rn(acc[mt][nt][0], acc[mt][nt][1]);
            if (row + 8 < M)
                C[(size_t)(row + 8) * 128 + pc] =
                    __floats2bfloat162_rn(acc[mt][nt][2], acc[mt][nt][3]);
        }
}

// ---- helpers for the gather ----
__device__ __forceinline__ void bf8_fma(uint4 v, float w, float* acc) {
    const __nv_bfloat162* p = (const __nv_bfloat162*)&v;
    #pragma unroll
    for (int j = 0; j < 4; j++) {
        float2 t2 = __bfloat1622float2(p[j]);
        acc[2 * j]     = fmaf(w, t2.x, acc[2 * j]);
        acc[2 * j + 1] = fmaf(w, t2.y, acc[2 * j + 1]);
    }
}

// ---------------- CSR gather (warp per node) + self-loop + bias + relu -> bf16 ----------------
__global__ void k_gather1(const uint4* __restrict__ H, uint4* __restrict__ out,
                          const int* __restrict__ rowstart, const int* __restrict__ csr,
                          const float* __restrict__ dinv,
                          const float* __restrict__ bias, int n) {
    int node = blockIdx.x * 8 + (threadIdx.x >> 5);
    if (node >= n) return;
    int lane = threadIdx.x & 31;              // cols [lane*8, lane*8+8)
    int r0 = rowstart[node], r1 = rowstart[node + 1];
    float di = dinv[node];
    float acc[8] = {};
    bf8_fma(H[(size_t)node * 32 + lane], di, acc);   // self loop
    int e = r0;
    for (; e + 1 < r1; e += 2) {
        int s0 = csr[e], s1 = csr[e + 1];
        float w0 = dinv[s0], w1 = dinv[s1];
        uint4 v0 = H[(size_t)s0 * 32 + lane];
        uint4 v1 = H[(size_t)s1 * 32 + lane];
        bf8_fma(v0, w0, acc);
        bf8_fma(v1, w1, acc);
    }
    if (e < r1) {
        int s0 = csr[e];
        bf8_fma(H[(size_t)s0 * 32 + lane], dinv[s0], acc);
    }
    float4 b0 = *(const float4*)(bias + lane * 8);
    float4 b1 = *(const float4*)(bias + lane * 8 + 4);
    float bb[8] = {b0.x, b0.y, b0.z, b0.w, b1.x, b1.y, b1.z, b1.w};
    __nv_bfloat162 r[4];
    #pragma unroll
    for (int j = 0; j < 4; j++) {
        float x0 = fmaxf(fmaf(di, acc[2 * j],     bb[2 * j]),     0.f);
        float x1 = fmaxf(fmaf(di, acc[2 * j + 1], bb[2 * j + 1]), 0.f);
        r[j] = __floats2bfloat162_rn(x0, x1);
    }
    out[(size_t)node * 32 + lane] = *(uint4*)r;
}

// ---------------- gather 2: same, but reduce directly into mean (no A2 buffer) ----------------
__global__ void k_gather2(const uint4* __restrict__ H,
                          const int* __restrict__ rowstart, const int* __restrict__ csr,
                          const float* __restrict__ dinv,
                          const float* __restrict__ bias,
                          float* __restrict__ mean, int n) {
    __shared__ float sm[8][256];
    int warp = threadIdx.x >> 5;
    int lane = threadIdx.x & 31;
    int node = blockIdx.x * 8 + warp;
    float res[8] = {};
    if (node < n) {
        int r0 = rowstart[node], r1 = rowstart[node + 1];
        float di = dinv[node];
        float acc[8] = {};
        bf8_fma(H[(size_t)node * 32 + lane], di, acc);
        int e = r0;
        for (; e + 1 < r1; e += 2) {
            int s0 = csr[e], s1 = csr[e + 1];
            float w0 = dinv[s0], w1 = dinv[s1];
            uint4 v0 = H[(size_t)s0 * 32 + lane];
            uint4 v1 = H[(size_t)s1 * 32 + lane];
            bf8_fma(v0, w0, acc);
            bf8_fma(v1, w1, acc);
        }
        if (e < r1) {
            int s0 = csr[e];
            bf8_fma(H[(size_t)s0 * 32 + lane], dinv[s0], acc);
        }
        float4 b0 = *(const float4*)(bias + lane * 8);
        float4 b1 = *(const float4*)(bias + lane * 8 + 4);
        float bb[8] = {b0.x, b0.y, b0.z, b0.w, b1.x, b1.y, b1.z, b1.w};
        #pragma unroll
        for (int j = 0; j < 8; j++)
            res[j] = fmaxf(fmaf(di, acc[j], bb[j]), 0.f);
    }
    #pragma unroll
    for (int j = 0; j < 8; j++) sm[warp][lane * 8 + j] = res[j];
    __syncthreads();
    int c = threadIdx.x;   // 256 columns
    float s = 0.f;
    #pragma unroll
    for (int w = 0; w < 8; w++) s += sm[w][c];
    atomicAdd(&mean[c], s);
}

// ---------------- MLP head ----------------
__global__ void k_head(const float* __restrict__ mean,
                       const float* __restrict__ fcW1, const float* __restrict__ fcb1,
                       const float* __restrict__ fcW2, const float* __restrict__ fcb2,
                       const float* __restrict__ fcW3, const float* __restrict__ fcb3,
                       float* __restrict__ out, int n) {
    __shared__ float g[256], h[256];
    int j = threadIdx.x;
    g[j] = fmaxf(mean[j] * (1.0f / (float)n), 0.f);
    __syncthreads();
    float s = fcb1[j];
    #pragma unroll 8
    for (int i = 0; i < 256; i++) s = fmaf(g[i], fcW1[i * 256 + j], s);
    h[j] = fmaxf(s, 0.f);
    __syncthreads();
    s = fcb2[j];
    #pragma unroll 8
    for (int i = 0; i < 256; i++) s = fmaf(h[i], fcW2[i * 256 + j], s);
    float g2 = fmaxf(s, 0.f);
    __syncthreads();
    g[j] = g2;
    __syncthreads();
    if (j < 64) {
        s = fcb3[j];
        #pragma unroll 8
        for (int i = 0; i < 256; i++) s = fmaf(g[i], fcW3[i * 64 + j], s);
        out[j] = s;
    }
}

extern "C" void kernel_launch(void* const* d_in, const int* in_sizes, int n_in,
                              void* d_out, int out_size) {
    const float* x    = (const float*)d_in[0];
    const int*   ei   = (const int*)  d_in[1];   // [2, E] int32
    const float* W1   = (const float*)d_in[2];
    const float* b1   = (const float*)d_in[3];
    const float* W2   = (const float*)d_in[4];
    const float* b2   = (const float*)d_in[5];
    const float* fcW1 = (const float*)d_in[6];
    const float* fcb1 = (const float*)d_in[7];
    const float* fcW2 = (const float*)d_in[8];
    const float* fcb2 = (const float*)d_in[9];
    const float* fcW3 = (const float*)d_in[10];
    const float* fcb3 = (const float*)d_in[11];
    float* out = (float*)d_out;

    int E = in_sizes[1] / 2;
    int N = in_sizes[0] / DIM;
    const int* src = ei;
    const int* dst = ei + E;

    __nv_bfloat16 *hbuf, *abuf;
    float *dinv, *mean;
    int *degi, *rowstart, *cursor, *csr;
    cudaGetSymbolAddress((void**)&hbuf, d_h);
    cudaGetSymbolAddress((void**)&abuf, d_a);
    cudaGetSymbolAddress((void**)&degi, d_degi);
    cudaGetSymbolAddress((void**)&dinv, d_dinv);
    cudaGetSymbolAddress((void**)&mean, d_mean);
    cudaGetSymbolAddress((void**)&rowstart, d_rowstart);
    cudaGetSymbolAddress((void**)&cursor, d_cursor);
    cudaGetSymbolAddress((void**)&csr, d_csr);

    // ---- CSR build + normalization ----
    cudaMemsetAsync(degi, 0, (size_t)N * sizeof(int));
    k_deg<<<(E + 255) / 256, 256>>>(dst, E, degi);
    k_scan<<<1, 1024>>>(degi, rowstart, cursor, dinv, N);
    k_fill<<<(E + 255) / 256, 256>>>(src, dst, cursor, csr, E);

    dim3 gg(2, (N + 127) / 128);
    unsigned gblocks = (unsigned)((N + 7) / 8);

    // ---- layer 1 ----
    k_gemm<false><<<gg, 256>>>(x, W1, (__nv_bfloat162*)hbuf, N);
    k_gather1<<<gblocks, 256>>>((const uint4*)hbuf, (uint4*)abuf,
                                rowstart, csr, dinv, b1, N);
    // ---- layer 2 (mean fused into gather) ----
    k_gemm<true><<<gg, 256>>>(abuf, W2, (__nv_bfloat162*)hbuf, N);
    cudaMemsetAsync(mean, 0, DIM * sizeof(float));
    k_gather2<<<gblocks, 256>>>((const uint4*)hbuf, rowstart, csr, dinv, b2,
                                mean, N);
    // ---- head ----
    k_head<<<1, 256>>>(mean, fcW1, fcb1, fcW2, fcb2, fcW3, fcb3, out, N);
}

// round 5
// speedup vs baseline: 2.3683x; 1.0393x over previous
#include <cuda_runtime.h>
#include <cuda_bf16.h>
#include <cstdint>

#define NN 50000
#define EE 800000
#define DIM 256

// ---- scratch (static device globals) ----
__device__ __nv_bfloat16 d_h[(size_t)NN * DIM];   // 25.6 MB
__device__ __nv_bfloat16 d_a[(size_t)NN * DIM];   // 25.6 MB
__device__ int   d_degi[NN];
__device__ float d_dinv[NN];
__device__ float d_mean[DIM];
__device__ int   d_rowstart[NN + 1];
__device__ int   d_cursor[NN];
__device__ int   d_csr[EE];

// ---------------- degree ----------------
__global__ void k_deg(const int* __restrict__ dst, int E, int* __restrict__ deg) {
    int e = blockIdx.x * blockDim.x + threadIdx.x;
    if (e < E) atomicAdd(&deg[dst[e]], 1);
}

// ---------------- fused scan: rowstart + cursor + dinv ----------------
__global__ void k_scan(const int* __restrict__ deg, int* __restrict__ rowstart,
                       int* __restrict__ cursor, float* __restrict__ dinv, int n) {
    __shared__ int partial[1024];
    int t = threadIdx.x;
    int chunk = (n + 1023) >> 10;
    int beg = t * chunk;
    int end = min(beg + chunk, n);
    int s = 0;
    for (int i = beg; i < end; i++) s += deg[i];
    partial[t] = s;
    __syncthreads();
    for (int off = 1; off < 1024; off <<= 1) {
        int add = (t >= off) ? partial[t - off] : 0;
        __syncthreads();
        partial[t] += add;
        __syncthreads();
    }
    int excl = (t == 0) ? 0 : partial[t - 1];
    for (int i = beg; i < end; i++) {
        rowstart[i] = excl;
        cursor[i] = excl;
        dinv[i] = rsqrtf((float)deg[i] + 1.0f);   // +1 = self loop
        excl += deg[i];
    }
    if (end == n) rowstart[n] = excl;
}

// ---------------- CSR fill ----------------
__global__ void k_fill(const int* __restrict__ src, const int* __restrict__ dst,
                       int* __restrict__ cursor, int* __restrict__ csr, int E) {
    int e = blockIdx.x * blockDim.x + threadIdx.x;
    if (e < E) {
        int pos = atomicAdd(&cursor[dst[e]], 1);
        csr[pos] = src[e];
    }
}

// ---------------- cp.async helpers ----------------
__device__ __forceinline__ void cp_async16(void* dst, const void* src, int sbytes) {
    unsigned d = (unsigned)__cvta_generic_to_shared(dst);
    asm volatile("cp.async.cg.shared.global [%0], [%1], 16, %2;"
                 :: "r"(d), "l"(src), "r"(sbytes));
}
__device__ __forceinline__ void cp_commit() {
    asm volatile("cp.async.commit_group;");
}
template <int N>
__device__ __forceinline__ void cp_wait() {
    asm volatile("cp.async.wait_group %0;" :: "n"(N));
}

__device__ __forceinline__ unsigned f2tf32(float f) {
    unsigned u;
    asm("cvt.rna.tf32.f32 %0, %1;" : "=r"(u) : "f"(f));
    return u;
}

// ---------------- TF32 GEMM, cp.async double-buffered, bf16 output ----------------
// smem layout (dynamic): Bs fp32[2][32][132] at 0 (33792 B), then A tiles.
// fp32 A: [2][128][36] fp32 (36864 B) ; bf16 A: [2][128][40] bf16 (20480 B)
template <bool BF16IN>
__global__ void __launch_bounds__(256, 2)
k_gemm(const void* __restrict__ Aptr, const float* __restrict__ B,
       __nv_bfloat162* __restrict__ C, int M) {
    extern __shared__ __align__(16) char smem[];
    float* BsBase = (float*)smem;                       // [2][32][132]
    char*  AsBase = smem + 2 * 32 * 132 * 4;            // A tiles

    int t = threadIdx.x;
    int lane = t & 31, wid = t >> 5;
    int wm = wid & 1, wn = wid >> 1;          // warp tile: 64x32
    int gi = lane >> 2, ti = lane & 3;
    int m0 = blockIdx.y * 128, n0 = blockIdx.x * 128;

    float acc[4][4][4] = {};

    auto loadTile = [&](int st, int k0) {
        float* Bs = BsBase + st * 32 * 132;
        #pragma unroll
        for (int i = 0; i < 4; i++) {
            int idx = t + i * 256;
            int br = idx >> 5, bc = (idx & 31) * 4;
            cp_async16(Bs + br * 132 + bc,
                       B + (size_t)(k0 + br) * 256 + n0 + bc, 16);
        }
        if (BF16IN) {
            const __nv_bfloat16* A = (const __nv_bfloat16*)Aptr;
            __nv_bfloat16* As = (__nv_bfloat16*)(AsBase + st * 128 * 80);
            #pragma unroll
            for (int i = 0; i < 2; i++) {
                int idx = t + i * 256;
                int ar = idx >> 2, ac = (idx & 3) * 8;
                int row = m0 + ar;
                int rc = min(row, M - 1);
                cp_async16(As + ar * 40 + ac,
                           A + (size_t)rc * 256 + k0 + ac, row < M ? 16 : 0);
            }
        } else {
            const float* A = (const float*)Aptr;
            float* As = (float*)(AsBase + st * 128 * 144);
            #pragma unroll
            for (int i = 0; i < 4; i++) {
                int idx = t + i * 256;
                int ar = idx >> 3, ac = (idx & 7) * 4;
                int row = m0 + ar;
                int rc = min(row, M - 1);
                cp_async16(As + ar * 36 + ac,
                           A + (size_t)rc * 256 + k0 + ac, row < M ? 16 : 0);
            }
        }
    };

    auto compute = [&](int st) {
        const float* Bs = BsBase + st * 32 * 132;
        #pragma unroll
        for (int kk = 0; kk < 4; kk++) {
            int kb = kk * 8;
            unsigned a[4][4], b[4][2];
            #pragma unroll
            for (int mt = 0; mt < 4; mt++) {
                int r = wm * 64 + mt * 16 + gi;
                if (BF16IN) {
                    const __nv_bfloat16* As =
                        (const __nv_bfloat16*)(AsBase + st * 128 * 80);
                    a[mt][0] = __float_as_uint(__bfloat162float(As[r * 40 + kb + ti]));
                    a[mt][1] = __float_as_uint(__bfloat162float(As[(r + 8) * 40 + kb + ti]));
                    a[mt][2] = __float_as_uint(__bfloat162float(As[r * 40 + kb + ti + 4]));
                    a[mt][3] = __float_as_uint(__bfloat162float(As[(r + 8) * 40 + kb + ti + 4]));
                } else {
                    const float* As = (const float*)(AsBase + st * 128 * 144);
                    a[mt][0] = f2tf32(As[r * 36 + kb + ti]);
                    a[mt][1] = f2tf32(As[(r + 8) * 36 + kb + ti]);
                    a[mt][2] = f2tf32(As[r * 36 + kb + ti + 4]);
                    a[mt][3] = f2tf32(As[(r + 8) * 36 + kb + ti + 4]);
                }
            }
            #pragma unroll
            for (int nt = 0; nt < 4; nt++) {
                int cn = wn * 32 + nt * 8 + gi;
                b[nt][0] = f2tf32(Bs[(kb + ti) * 132 + cn]);
                b[nt][1] = f2tf32(Bs[(kb + ti + 4) * 132 + cn]);
            }
            #pragma unroll
            for (int mt = 0; mt < 4; mt++)
                #pragma unroll
                for (int nt = 0; nt < 4; nt++)
                    asm volatile(
                        "mma.sync.aligned.m16n8k8.row.col.f32.tf32.tf32.f32 "
                        "{%0,%1,%2,%3}, {%4,%5,%6,%7}, {%8,%9}, {%0,%1,%2,%3};"
                        : "+f"(acc[mt][nt][0]), "+f"(acc[mt][nt][1]),
                          "+f"(acc[mt][nt][2]), "+f"(acc[mt][nt][3])
                        : "r"(a[mt][0]), "r"(a[mt][1]), "r"(a[mt][2]), "r"(a[mt][3]),
                          "r"(b[nt][0]), "r"(b[nt][1]));
        }
    };

    loadTile(0, 0);
    cp_commit();
    #pragma unroll
    for (int i = 0; i < 8; i++) {
        if (i + 1 < 8) { loadTile((i + 1) & 1, (i + 1) * 32); cp_commit(); }
        if (i + 1 < 8) cp_wait<1>(); else cp_wait<0>();
        __syncthreads();
        compute(i & 1);
        __syncthreads();
    }

    #pragma unroll
    for (int mt = 0; mt < 4; mt++)
        #pragma unroll
        for (int nt = 0; nt < 4; nt++) {
            int row = m0 + wm * 64 + mt * 16 + gi;
            int pc = n0 / 2 + wn * 16 + nt * 4 + ti;
            if (row < M)
                C[(size_t)row * 128 + pc] =
                    __floats2bfloat162_rn(acc[mt][nt][0], acc[mt][nt][1]);
            if (row + 8 < M)
                C[(size_t)(row + 8) * 128 + pc] =
                    __floats2bfloat162_rn(acc[mt][nt][2], acc[mt][nt][3]);
        }
}

// ---- helpers for the gather ----
__device__ __forceinline__ void bf8_fma(uint4 v, float w, float* acc) {
    const __nv_bfloat162* p = (const __nv_bfloat162*)&v;
    #pragma unroll
    for (int j = 0; j < 4; j++) {
        float2 t2 = __bfloat1622float2(p[j]);
        acc[2 * j]     = fmaf(w, t2.x, acc[2 * j]);
        acc[2 * j + 1] = fmaf(w, t2.y, acc[2 * j + 1]);
    }
}

// ---------------- CSR gather (warp per node) + self-loop + bias + relu -> bf16 ----------------
__global__ void k_gather1(const uint4* __restrict__ H, uint4* __restrict__ out,
                          const int* __restrict__ rowstart, const int* __restrict__ csr,
                          const float* __restrict__ dinv,
                          const float* __restrict__ bias, int n) {
    int node = blockIdx.x * 8 + (threadIdx.x >> 5);
    if (node >= n) return;
    int lane = threadIdx.x & 31;
    int r0 = rowstart[node], r1 = rowstart[node + 1];
    float di = dinv[node];
    float acc[8] = {};
    bf8_fma(H[(size_t)node * 32 + lane], di, acc);   // self loop
    int e = r0;
    for (; e + 1 < r1; e += 2) {
        int s0 = csr[e], s1 = csr[e + 1];
        float w0 = dinv[s0], w1 = dinv[s1];
        uint4 v0 = H[(size_t)s0 * 32 + lane];
        uint4 v1 = H[(size_t)s1 * 32 + lane];
        bf8_fma(v0, w0, acc);
        bf8_fma(v1, w1, acc);
    }
    if (e < r1) {
        int s0 = csr[e];
        bf8_fma(H[(size_t)s0 * 32 + lane], dinv[s0], acc);
    }
    float4 b0 = *(const float4*)(bias + lane * 8);
    float4 b1 = *(const float4*)(bias + lane * 8 + 4);
    float bb[8] = {b0.x, b0.y, b0.z, b0.w, b1.x, b1.y, b1.z, b1.w};
    __nv_bfloat162 r[4];
    #pragma unroll
    for (int j = 0; j < 4; j++) {
        float x0 = fmaxf(fmaf(di, acc[2 * j],     bb[2 * j]),     0.f);
        float x1 = fmaxf(fmaf(di, acc[2 * j + 1], bb[2 * j + 1]), 0.f);
        r[j] = __floats2bfloat162_rn(x0, x1);
    }
    out[(size_t)node * 32 + lane] = *(uint4*)r;
}

// ---------------- gather 2: reduce directly into mean ----------------
__global__ void k_gather2(const uint4* __restrict__ H,
                          const int* __restrict__ rowstart, const int* __restrict__ csr,
                          const float* __restrict__ dinv,
                          const float* __restrict__ bias,
                          float* __restrict__ mean, int n) {
    __shared__ float sm[8][256];
    int warp = threadIdx.x >> 5;
    int lane = threadIdx.x & 31;
    int node = blockIdx.x * 8 + warp;
    float res[8] = {};
    if (node < n) {
        int r0 = rowstart[node], r1 = rowstart[node + 1];
        float di = dinv[node];
        float acc[8] = {};
        bf8_fma(H[(size_t)node * 32 + lane], di, acc);
        int e = r0;
        for (; e + 1 < r1; e += 2) {
            int s0 = csr[e], s1 = csr[e + 1];
            float w0 = dinv[s0], w1 = dinv[s1];
            uint4 v0 = H[(size_t)s0 * 32 + lane];
            uint4 v1 = H[(size_t)s1 * 32 + lane];
            bf8_fma(v0, w0, acc);
            bf8_fma(v1, w1, acc);
        }
        if (e < r1) {
            int s0 = csr[e];
            bf8_fma(H[(size_t)s0 * 32 + lane], dinv[s0], acc);
        }
        float4 b0 = *(const float4*)(bias + lane * 8);
        float4 b1 = *(const float4*)(bias + lane * 8 + 4);
        float bb[8] = {b0.x, b0.y, b0.z, b0.w, b1.x, b1.y, b1.z, b1.w};
        #pragma unroll
        for (int j = 0; j < 8; j++)
            res[j] = fmaxf(fmaf(di, acc[j], bb[j]), 0.f);
    }
    #pragma unroll
    for (int j = 0; j < 8; j++) sm[warp][lane * 8 + j] = res[j];
    __syncthreads();
    int c = threadIdx.x;
    float s = 0.f;
    #pragma unroll
    for (int w = 0; w < 8; w++) s += sm[w][c];
    atomicAdd(&mean[c], s);
}

// ---------------- MLP head ----------------
__global__ void k_head(const float* __restrict__ mean,
                       const float* __restrict__ fcW1, const float* __restrict__ fcb1,
                       const float* __restrict__ fcW2, const float* __restrict__ fcb2,
                       const float* __restrict__ fcW3, const float* __restrict__ fcb3,
                       float* __restrict__ out, int n) {
    __shared__ float g[256], h[256];
    int j = threadIdx.x;
    g[j] = fmaxf(mean[j] * (1.0f / (float)n), 0.f);
    __syncthreads();
    float s = fcb1[j];
    #pragma unroll 8
    for (int i = 0; i < 256; i++) s = fmaf(g[i], fcW1[i * 256 + j], s);
    h[j] = fmaxf(s, 0.f);
    __syncthreads();
    s = fcb2[j];
    #pragma unroll 8
    for (int i = 0; i < 256; i++) s = fmaf(h[i], fcW2[i * 256 + j], s);
    float g2 = fmaxf(s, 0.f);
    __syncthreads();
    g[j] = g2;
    __syncthreads();
    if (j < 64) {
        s = fcb3[j];
        #pragma unroll 8
        for (int i = 0; i < 256; i++) s = fmaf(g[i], fcW3[i * 64 + j], s);
        out[j] = s;
    }
}

extern "C" void kernel_launch(void* const* d_in, const int* in_sizes, int n_in,
                              void* d_out, int out_size) {
    const float* x    = (const float*)d_in[0];
    const int*   ei   = (const int*)  d_in[1];   // [2, E] int32
    const float* W1   = (const float*)d_in[2];
    const float* b1   = (const float*)d_in[3];
    const float* W2   = (const float*)d_in[4];
    const float* b2   = (const float*)d_in[5];
    const float* fcW1 = (const float*)d_in[6];
    const float* fcb1 = (const float*)d_in[7];
    const float* fcW2 = (const float*)d_in[8];
    const float* fcb2 = (const float*)d_in[9];
    const float* fcW3 = (const float*)d_in[10];
    const float* fcb3 = (const float*)d_in[11];
    float* out = (float*)d_out;

    int E = in_sizes[1] / 2;
    int N = in_sizes[0] / DIM;
    const int* src = ei;
    const int* dst = ei + E;

    __nv_bfloat16 *hbuf, *abuf;
    float *dinv, *mean;
    int *degi, *rowstart, *cursor, *csr;
    cudaGetSymbolAddress((void**)&hbuf, d_h);
    cudaGetSymbolAddress((void**)&abuf, d_a);
    cudaGetSymbolAddress((void**)&degi, d_degi);
    cudaGetSymbolAddress((void**)&dinv, d_dinv);
    cudaGetSymbolAddress((void**)&mean, d_mean);
    cudaGetSymbolAddress((void**)&rowstart, d_rowstart);
    cudaGetSymbolAddress((void**)&cursor, d_cursor);
    cudaGetSymbolAddress((void**)&csr, d_csr);

    // dynamic smem opt-in for the GEMMs
    const int SMEM32 = 2 * 32 * 132 * 4 + 2 * 128 * 144;  // 70656
    const int SMEM16 = 2 * 32 * 132 * 4 + 2 * 128 * 80;   // 54272
    cudaFuncSetAttribute(k_gemm<false>,
                         cudaFuncAttributeMaxDynamicSharedMemorySize, SMEM32);
    cudaFuncSetAttribute(k_gemm<true>,
                         cudaFuncAttributeMaxDynamicSharedMemorySize, SMEM16);

    // side stream + events (created once; host-side resources only)
    static cudaStream_t s_side = nullptr;
    static cudaEvent_t ev_fork = nullptr, ev_join = nullptr;
    if (s_side == nullptr) {
        cudaStreamCreateWithFlags(&s_side, cudaStreamNonBlocking);
        cudaEventCreateWithFlags(&ev_fork, cudaEventDisableTiming);
        cudaEventCreateWithFlags(&ev_join, cudaEventDisableTiming);
    }

    dim3 gg(2, (N + 127) / 128);
    unsigned gblocks = (unsigned)((N + 7) / 8);

    // ---- fork: CSR build on side stream, concurrent with GEMM-1 ----
    cudaEventRecord(ev_fork, 0);
    cudaStreamWaitEvent(s_side, ev_fork, 0);
    cudaMemsetAsync(degi, 0, (size_t)N * sizeof(int), s_side);
    k_deg<<<(E + 255) / 256, 256, 0, s_side>>>(dst, E, degi);
    k_scan<<<1, 1024, 0, s_side>>>(degi, rowstart, cursor, dinv, N);
    k_fill<<<(E + 255) / 256, 256, 0, s_side>>>(src, dst, cursor, csr, E);
    cudaEventRecord(ev_join, s_side);

    // main stream: GEMM-1 + mean clear
    cudaMemsetAsync(mean, 0, DIM * sizeof(float));
    k_gemm<false><<<gg, 256, SMEM32>>>(x, W1, (__nv_bfloat162*)hbuf, N);

    // join before the gather needs the CSR
    cudaStreamWaitEvent(0, ev_join, 0);

    // ---- layer 1 aggregation ----
    k_gather1<<<gblocks, 256>>>((const uint4*)hbuf, (uint4*)abuf,
                                rowstart, csr, dinv, b1, N);
    // ---- layer 2 (mean fused into gather) ----
    k_gemm<true><<<gg, 256, SMEM16>>>(abuf, W2, (__nv_bfloat162*)hbuf, N);
    k_gather2<<<gblocks, 256>>>((const uint4*)hbuf, rowstart, csr, dinv, b2,
                                mean, N);
    // ---- head ----
    k_head<<<1, 256>>>(mean, fcW1, fcb1, fcW2, fcb2, fcW3, fcb3, out, N);
}